// round 1
// baseline (speedup 1.0000x reference)
#include <cuda_runtime.h>
#include <cstddef>

// Problem constants
#define B_   4
#define C_   256
#define H_   64
#define W_   64
#define OC_  256
#define K_   9
#define P_   4096          // H*W
#define CK_  2304          // C*K
#define NCHUNK 4           // channel chunks for offset conv

// ---------------- scratch (device globals; no allocs allowed) ----------------
__device__ float g_part[NCHUNK * B_ * 27 * P_];          // partial offset-conv sums
__device__ float g_sx  [B_ * K_ * P_];
__device__ float g_sy  [B_ * K_ * P_];
__device__ float g_mask[B_ * K_ * P_];
__device__ float g_col [(size_t)B_ * CK_ * P_];          // im2col buffer (~151MB)

// ---------------- kernel 1: offset-predictor conv (27ch, 3x3, pad1) ----------
// grid (16384/128, NCHUNK), block 128. Each thread: one output pixel, 27 accs,
// over 64 channels of this chunk. Weights staged per-c in smem (padded to 12).
__global__ __launch_bounds__(128) void k_offconv(const float* __restrict__ x,
                                                 const float* __restrict__ ow) {
    const int tid  = threadIdx.x;
    const int gpix = blockIdx.x * 128 + tid;   // 0..16383
    const int b  = gpix >> 12;
    const int p  = gpix & (P_ - 1);
    const int py = p >> 6;
    const int px = p & 63;
    const int c0 = blockIdx.y * (C_ / NCHUNK);

    __shared__ float ws[27 * 12];

    float acc[27];
#pragma unroll
    for (int i = 0; i < 27; i++) acc[i] = 0.f;

    const float* xb = x + (size_t)b * C_ * P_;

    for (int cc = 0; cc < C_ / NCHUNK; cc++) {
        const int c = c0 + cc;
        __syncthreads();
        for (int i = tid; i < 243; i += 128) {
            int ch = i / 9, t = i - ch * 9;
            ws[ch * 12 + t] = ow[ch * CK_ + c * 9 + t];
        }
        __syncthreads();

        // 3x3 neighborhood with zero pad
        float xv[9];
        const float* xc = xb + (size_t)c * P_;
#pragma unroll
        for (int ky = 0; ky < 3; ky++) {
            const int yy = py + ky - 1;
            const bool yok = ((unsigned)yy < (unsigned)H_);
#pragma unroll
            for (int kx = 0; kx < 3; kx++) {
                const int xx = px + kx - 1;
                const bool ok = yok && ((unsigned)xx < (unsigned)W_);
                xv[ky * 3 + kx] = ok ? xc[yy * W_ + xx] : 0.f;
            }
        }
#pragma unroll
        for (int ch = 0; ch < 27; ch++) {
            const float* wp = &ws[ch * 12];
            float s = acc[ch];
#pragma unroll
            for (int t = 0; t < 9; t++) s += xv[t] * wp[t];
            acc[ch] = s;
        }
    }

    const size_t base = (((size_t)blockIdx.y * B_ + b) * 27) * P_ + p;
#pragma unroll
    for (int ch = 0; ch < 27; ch++) g_part[base + (size_t)ch * P_] = acc[ch];
}

// ---------------- kernel 2: reduce chunks, add bias, build sx/sy/mask --------
__global__ __launch_bounds__(256) void k_prep(const float* __restrict__ ob) {
    const int idx = blockIdx.x * 256 + threadIdx.x;   // over B*K*P = 147456
    if (idx >= B_ * K_ * P_) return;
    const int p  = idx & (P_ - 1);
    const int bk = idx >> 12;
    const int b  = bk / K_;
    const int k  = bk - b * K_;

    float ox = 0.f, oy = 0.f, om = 0.f;
#pragma unroll
    for (int ch = 0; ch < NCHUNK; ch++) {
        const size_t base = (((size_t)ch * B_ + b) * 27) * P_ + p;
        ox += g_part[base + (size_t)k * P_];
        oy += g_part[base + (size_t)(9 + k) * P_];
        om += g_part[base + (size_t)(18 + k) * P_];
    }
    ox += ob[k];
    oy += ob[9 + k];
    om += ob[18 + k];

    const int py = p >> 6, px = p & 63;
    const int kx = k % 3, ky = k / 3;

    // sx = px*1 - pad + (kx-1)*dil + offx ; same for sy with ky/offy
    g_sx[idx]   = (float)(px - 1 + (kx - 1)) + ox;
    g_sy[idx]   = (float)(py - 1 + (ky - 1)) + oy;
    g_mask[idx] = 1.f / (1.f + expf(-om));
}

// ---------------- kernel 3: bilinear im2col with mask modulation -------------
// One thread per (b,k,p): compute 4 corner indices/weights once, loop 256 chans.
__global__ __launch_bounds__(256) void k_im2col(const float* __restrict__ x) {
    const int idx = blockIdx.x * 256 + threadIdx.x;
    if (idx >= B_ * K_ * P_) return;
    const int p  = idx & (P_ - 1);
    const int bk = idx >> 12;
    const int b  = bk / K_;
    const int k  = bk - b * K_;

    const float sx = g_sx[idx];
    const float sy = g_sy[idx];
    const float m  = g_mask[idx];

    const float x0f = floorf(sx);
    const float y0f = floorf(sy);
    const int x0 = (int)x0f;
    const int y0 = (int)y0f;
    const float wx1 = sx - x0f, wy1 = sy - y0f;
    const float wx0 = 1.f - wx1, wy0 = 1.f - wy1;

    const bool vx0 = (x0 >= 0)     && (x0 <= W_ - 1);
    const bool vx1 = (x0 + 1 >= 0) && (x0 + 1 <= W_ - 1);
    const bool vy0 = (y0 >= 0)     && (y0 <= H_ - 1);
    const bool vy1 = (y0 + 1 >= 0) && (y0 + 1 <= H_ - 1);

    const int cx0 = min(max(x0, 0), W_ - 1);
    const int cx1 = min(max(x0 + 1, 0), W_ - 1);
    const int cy0 = min(max(y0, 0), H_ - 1);
    const int cy1 = min(max(y0 + 1, 0), H_ - 1);

    const float w00 = wx0 * wy0 * ((vx0 && vy0) ? m : 0.f);
    const float w01 = wx1 * wy0 * ((vx1 && vy0) ? m : 0.f);
    const float w10 = wx0 * wy1 * ((vx0 && vy1) ? m : 0.f);
    const float w11 = wx1 * wy1 * ((vx1 && vy1) ? m : 0.f);

    const int i00 = cy0 * W_ + cx0;
    const int i01 = cy0 * W_ + cx1;
    const int i10 = cy1 * W_ + cx0;
    const int i11 = cy1 * W_ + cx1;

    const float* xb = x + (size_t)b * C_ * P_;
    float* colp = g_col + ((size_t)b * CK_ + k) * P_ + p;   // +c*9*P_ per channel

#pragma unroll 4
    for (int c = 0; c < C_; c++) {
        const float* xc = xb + (size_t)c * P_;
        const float v = w00 * xc[i00] + w01 * xc[i01] +
                        w10 * xc[i10] + w11 * xc[i11];
        colp[(size_t)c * (K_ * P_)] = v;
    }
}

// ---------------- kernel 4: SGEMM  out[b,o,p] = W[o,ck]*col[b,ck,p] + bias ---
// 128x128 tile, BK=8, 256 threads, 8x8 per thread, double-buffered smem.
__global__ __launch_bounds__(256) void k_gemm(const float* __restrict__ Wm,
                                              const float* __restrict__ bias,
                                              float* __restrict__ out) {
    const int b  = blockIdx.z;
    const float* col = g_col + (size_t)b * CK_ * P_;
    float* outp = out + (size_t)b * OC_ * P_;

    const int n0  = blockIdx.x * 128;
    const int m0  = blockIdx.y * 128;
    const int tid = threadIdx.x;

    __shared__ float As[2][8][128];
    __shared__ float Bs[2][8][128];

    const int arow = tid >> 1;
    const int acol = (tid & 1) << 2;
    const int brow = tid >> 5;
    const int bcol = (tid & 31) << 2;

    // prologue: load k0=0 tile into buffer 0
    {
        const float4 av = *(const float4*)(Wm + (size_t)(m0 + arow) * CK_ + acol);
        As[0][acol + 0][arow] = av.x;
        As[0][acol + 1][arow] = av.y;
        As[0][acol + 2][arow] = av.z;
        As[0][acol + 3][arow] = av.w;
        const float4 bv = *(const float4*)(col + (size_t)brow * P_ + n0 + bcol);
        *(float4*)&Bs[0][brow][bcol] = bv;
    }
    __syncthreads();

    float acc[8][8];
#pragma unroll
    for (int i = 0; i < 8; i++)
#pragma unroll
        for (int j = 0; j < 8; j++) acc[i][j] = 0.f;

    const int ty = tid >> 4;
    const int tx = tid & 15;
    const int mr = ty << 3;
    const int nc = tx << 3;

    for (int k0 = 0; k0 < CK_; k0 += 8) {
        const int buf = (k0 >> 3) & 1;
        const bool pref = (k0 + 8 < CK_);
        float4 av, bv;
        if (pref) {
            av = *(const float4*)(Wm + (size_t)(m0 + arow) * CK_ + (k0 + 8) + acol);
            bv = *(const float4*)(col + (size_t)(k0 + 8 + brow) * P_ + n0 + bcol);
        }
#pragma unroll
        for (int kk = 0; kk < 8; kk++) {
            float a[8], bb[8];
            *(float4*)&a[0]  = *(const float4*)&As[buf][kk][mr];
            *(float4*)&a[4]  = *(const float4*)&As[buf][kk][mr + 4];
            *(float4*)&bb[0] = *(const float4*)&Bs[buf][kk][nc];
            *(float4*)&bb[4] = *(const float4*)&Bs[buf][kk][nc + 4];
#pragma unroll
            for (int i = 0; i < 8; i++)
#pragma unroll
                for (int j = 0; j < 8; j++) acc[i][j] += a[i] * bb[j];
        }
        if (pref) {
            const int nbuf = buf ^ 1;
            As[nbuf][acol + 0][arow] = av.x;
            As[nbuf][acol + 1][arow] = av.y;
            As[nbuf][acol + 2][arow] = av.z;
            As[nbuf][acol + 3][arow] = av.w;
            *(float4*)&Bs[nbuf][brow][bcol] = bv;
        }
        __syncthreads();
    }

    // epilogue: + bias, vectorized stores
#pragma unroll
    for (int i = 0; i < 8; i++) {
        const int o = m0 + mr + i;
        const float bvv = bias[o];
        float4 r0, r1;
        r0.x = acc[i][0] + bvv; r0.y = acc[i][1] + bvv;
        r0.z = acc[i][2] + bvv; r0.w = acc[i][3] + bvv;
        r1.x = acc[i][4] + bvv; r1.y = acc[i][5] + bvv;
        r1.z = acc[i][6] + bvv; r1.w = acc[i][7] + bvv;
        float* op = outp + (size_t)o * P_ + n0 + nc;
        *(float4*)op       = r0;
        *(float4*)(op + 4) = r1;
    }
}

// ---------------- launch ----------------
extern "C" void kernel_launch(void* const* d_in, const int* in_sizes, int n_in,
                              void* d_out, int out_size) {
    const float* x    = (const float*)d_in[0];   // [4,256,64,64]
    const float* ow   = (const float*)d_in[1];   // [27,256,3,3]
    const float* ob   = (const float*)d_in[2];   // [27]
    const float* wgt  = (const float*)d_in[3];   // [256,256,3,3]
    const float* bias = (const float*)d_in[4];   // [256]
    float* out = (float*)d_out;                  // [4,256,64,64]

    k_offconv<<<dim3((B_ * P_) / 128, NCHUNK), 128>>>(x, ow);
    k_prep<<<(B_ * K_ * P_) / 256, 256>>>(ob);
    k_im2col<<<(B_ * K_ * P_) / 256, 256>>>(x);
    k_gemm<<<dim3(P_ / 128, OC_ / 128, B_), 256>>>(wgt, bias, out);
}

// round 3
// speedup vs baseline: 2.0877x; 2.0877x over previous
#include <cuda_runtime.h>
#include <cuda_bf16.h>
#include <cstdint>
#include <cstddef>

// Problem constants
#define B_   4
#define C_   256
#define H_   64
#define W_   64
#define OC_  256
#define K_   9
#define P_   4096          // H*W
#define CK_  2304          // C*K
#define KT_  36            // number of K-chunks of 64
#define TK_  64
#define NCHUNK 4

// tcgen05 is arch-specific ("a"/family targets only). The build includes a
// generic compute_103 PTX pass where those instructions are illegal -- guard
// them out there; the sm_103a cubin (what actually runs) gets the real code.
#if defined(__CUDA_ARCH_FEAT_SM103_ALL) || defined(__CUDA_ARCH_FEAT_SM100_ALL) || \
    defined(__CUDA_ARCH_FEAT_SM101_ALL) || defined(__CUDA_ARCH_SPECIFIC__) ||     \
    defined(__CUDA_ARCH_FAMILY_SPECIFIC__)
#define HAS_TC 1
#else
#define HAS_TC 0
#endif

// ---------------- scratch (device globals) ----------------
__device__ float g_part[NCHUNK * B_ * 27 * P_];
__device__ float g_sx  [B_ * K_ * P_];
__device__ float g_sy  [B_ * K_ * P_];
__device__ float g_mask[B_ * K_ * P_];
// blocked col buffers: [b][kt][p][64] bf16, 128B K-major rows
__device__ __align__(16) __nv_bfloat16 g_colh[(size_t)B_ * KT_ * P_ * TK_];
__device__ __align__(16) __nv_bfloat16 g_coll[(size_t)B_ * KT_ * P_ * TK_];
// blocked weights: [kt][oc][64] bf16
__device__ __align__(16) __nv_bfloat16 g_wh[(size_t)KT_ * OC_ * TK_];
__device__ __align__(16) __nv_bfloat16 g_wl[(size_t)KT_ * OC_ * TK_];

// ==================== PTX helpers ====================
__device__ __forceinline__ uint32_t smem_u32(const void* p) {
    uint32_t a;
    asm("{ .reg .u64 t; cvta.to.shared.u64 t, %1; cvt.u32.u64 %0, t; }" : "=r"(a) : "l"(p));
    return a;
}
__device__ __forceinline__ uint32_t elect1() {
    uint32_t p;
    asm volatile("{\n .reg .pred p;\n elect.sync _|p, 0xFFFFFFFF;\n selp.b32 %0,1,0,p;\n}" : "=r"(p));
    return p;
}
#define MBARRIER_INIT(addr, cnt) \
    asm volatile("mbarrier.init.shared.b64 [%0], %1;" :: "r"(addr), "r"((uint32_t)(cnt)) : "memory")
#define MBAR_INVAL(addr) \
    asm volatile("mbarrier.inval.shared.b64 [%0];" :: "r"(addr) : "memory")
#define MBARRIER_WAIT_PARITY(mbar, par) do {                                   \
    uint32_t _m = (mbar); uint32_t _p = (uint32_t)(par); uint32_t _d;          \
    asm volatile("{\n .reg .pred p;\n"                                         \
        " mbarrier.try_wait.parity.acquire.cta.shared::cta.b64 p, [%1], %2;\n" \
        " selp.b32 %0, 1, 0, p;\n}" : "=r"(_d) : "r"(_m), "r"(_p) : "memory"); \
    if (!_d) {                                                                 \
        asm volatile("{\n .reg .pred P1;\n"                                    \
            "WL_%=:\n"                                                         \
            " mbarrier.try_wait.parity.acquire.cta.shared::cta.b64 P1, [%0], %1, 0x989680;\n" \
            " @P1 bra.uni WD_%=;\n bra.uni WL_%=;\nWD_%=:\n}"                  \
            :: "r"(_m), "r"(_p) : "memory");                                   \
    }                                                                          \
} while (0)

#if HAS_TC
#define TCGEN05_ALLOC(sa, n) \
    asm volatile("tcgen05.alloc.cta_group::1.sync.aligned.shared::cta.b32 [%0], %1;" \
        :: "r"((uint32_t)(sa)), "r"((uint32_t)(n)) : "memory")
#define TCGEN05_DEALLOC(t, n) \
    asm volatile("tcgen05.dealloc.cta_group::1.sync.aligned.b32 %0, %1;" :: "r"(t), "r"((uint32_t)(n)))
#define TCGEN05_RELINQ() \
    asm volatile("tcgen05.relinquish_alloc_permit.cta_group::1.sync.aligned;")
#define TCGEN05_COMMIT(mbar) \
    asm volatile("tcgen05.commit.cta_group::1.mbarrier::arrive::one.shared::cluster.b64 [%0];" \
        :: "r"((uint32_t)(mbar)) : "memory")
#define TCGEN05_FENCE_AFTER()  asm volatile("tcgen05.fence::after_thread_sync;" ::: "memory")
#define TCGEN05_FENCE_BEFORE() asm volatile("tcgen05.fence::before_thread_sync;" ::: "memory")
#define TCGEN05_WAIT_LD()      asm volatile("tcgen05.wait::ld.sync.aligned;" ::: "memory")
#define TCGEN05_LD_X32(r, ta) \
    asm volatile("tcgen05.ld.sync.aligned.32x32b.x32.b32 " \
        "{%0,%1,%2,%3,%4,%5,%6,%7,%8,%9,%10,%11,%12,%13,%14,%15," \
        "%16,%17,%18,%19,%20,%21,%22,%23,%24,%25,%26,%27,%28,%29,%30,%31}, [%32];" \
        : "=r"((r)[0]),"=r"((r)[1]),"=r"((r)[2]),"=r"((r)[3]),"=r"((r)[4]),"=r"((r)[5]),"=r"((r)[6]),"=r"((r)[7]), \
          "=r"((r)[8]),"=r"((r)[9]),"=r"((r)[10]),"=r"((r)[11]),"=r"((r)[12]),"=r"((r)[13]),"=r"((r)[14]),"=r"((r)[15]), \
          "=r"((r)[16]),"=r"((r)[17]),"=r"((r)[18]),"=r"((r)[19]),"=r"((r)[20]),"=r"((r)[21]),"=r"((r)[22]),"=r"((r)[23]), \
          "=r"((r)[24]),"=r"((r)[25]),"=r"((r)[26]),"=r"((r)[27]),"=r"((r)[28]),"=r"((r)[29]),"=r"((r)[30]),"=r"((r)[31]) \
        : "r"(ta))
#endif

// SW128 K-major descriptor (layout=2, version=1, SBO=64, LBO=1)
__device__ __forceinline__ uint64_t sdesc(uint32_t addr) {
    return 0x4000404000010000ull | (uint64_t)((addr >> 4) & 0x3FFF);
}
// idesc: D=f32, A=bf16, B=bf16, N=256, M=128, K-major both
#define IDESC_ 0x8400490u

__device__ __forceinline__ void mma_bf16_ss(uint32_t d, uint64_t ad, uint64_t bd, uint32_t en) {
#if HAS_TC
    asm volatile("{\n .reg .pred p;\n setp.ne.u32 p, %5, 0;\n"
        " tcgen05.mma.cta_group::1.kind::f16 [%0], %1, %2, %3, {%4,%4,%4,%4}, p;\n}"
        :: "r"(d), "l"(ad), "l"(bd), "r"(IDESC_), "r"(0u), "r"(en) : "memory");
#endif
}

// ---------------- kernel 1: offset-predictor conv (27ch, 3x3, pad1) ----------
__global__ __launch_bounds__(128) void k_offconv(const float* __restrict__ x,
                                                 const float* __restrict__ ow) {
    const int tid  = threadIdx.x;
    const int gpix = blockIdx.x * 128 + tid;
    const int b  = gpix >> 12;
    const int p  = gpix & (P_ - 1);
    const int py = p >> 6;
    const int px = p & 63;
    const int c0 = blockIdx.y * (C_ / NCHUNK);

    __shared__ float ws[27 * 12];

    float acc[27];
#pragma unroll
    for (int i = 0; i < 27; i++) acc[i] = 0.f;

    const float* xb = x + (size_t)b * C_ * P_;

    for (int cc = 0; cc < C_ / NCHUNK; cc++) {
        const int c = c0 + cc;
        __syncthreads();
        for (int i = tid; i < 243; i += 128) {
            int ch = i / 9, t = i - ch * 9;
            ws[ch * 12 + t] = ow[ch * CK_ + c * 9 + t];
        }
        __syncthreads();

        float xv[9];
        const float* xc = xb + (size_t)c * P_;
#pragma unroll
        for (int ky = 0; ky < 3; ky++) {
            const int yy = py + ky - 1;
            const bool yok = ((unsigned)yy < (unsigned)H_);
#pragma unroll
            for (int kx = 0; kx < 3; kx++) {
                const int xx = px + kx - 1;
                const bool ok = yok && ((unsigned)xx < (unsigned)W_);
                xv[ky * 3 + kx] = ok ? xc[yy * W_ + xx] : 0.f;
            }
        }
#pragma unroll
        for (int ch = 0; ch < 27; ch++) {
            const float* wp = &ws[ch * 12];
            float s = acc[ch];
#pragma unroll
            for (int t = 0; t < 9; t++) s += xv[t] * wp[t];
            acc[ch] = s;
        }
    }

    const size_t base = (((size_t)blockIdx.y * B_ + b) * 27) * P_ + p;
#pragma unroll
    for (int ch = 0; ch < 27; ch++) g_part[base + (size_t)ch * P_] = acc[ch];
}

// ---------------- kernel 2: reduce chunks, add bias, build sx/sy/mask --------
__global__ __launch_bounds__(256) void k_prep(const float* __restrict__ ob) {
    const int idx = blockIdx.x * 256 + threadIdx.x;
    if (idx >= B_ * K_ * P_) return;
    const int p  = idx & (P_ - 1);
    const int bk = idx >> 12;
    const int b  = bk / K_;
    const int k  = bk - b * K_;

    float ox = 0.f, oy = 0.f, om = 0.f;
#pragma unroll
    for (int ch = 0; ch < NCHUNK; ch++) {
        const size_t base = (((size_t)ch * B_ + b) * 27) * P_ + p;
        ox += g_part[base + (size_t)k * P_];
        oy += g_part[base + (size_t)(9 + k) * P_];
        om += g_part[base + (size_t)(18 + k) * P_];
    }
    ox += ob[k];
    oy += ob[9 + k];
    om += ob[18 + k];

    const int py = p >> 6, px = p & 63;
    const int kx = k % 3, ky = k / 3;

    g_sx[idx]   = (float)(px - 1 + (kx - 1)) + ox;
    g_sy[idx]   = (float)(py - 1 + (ky - 1)) + oy;
    g_mask[idx] = 1.f / (1.f + expf(-om));
}

// ---------------- kernel 3: weight split fp32 -> bf16 hi/lo, blocked ---------
__global__ __launch_bounds__(256) void k_wsplit(const float* __restrict__ w) {
    const int idx = blockIdx.x * 256 + threadIdx.x;  // < OC_*CK_
    const int oc = idx / CK_;
    const int g  = idx - oc * CK_;
    const int kt = g >> 6, ck = g & 63;
    const float v = w[idx];
    const __nv_bfloat16 h = __float2bfloat16(v);
    const __nv_bfloat16 l = __float2bfloat16(v - __bfloat162float(h));
    const size_t o = ((size_t)kt * OC_ + oc) * 64 + ck;
    g_wh[o] = h;
    g_wl[o] = l;
}

// ---------------- kernel 4: bilinear im2col -> blocked bf16 hi/lo tiles ------
__global__ __launch_bounds__(256) void k_im2col_tc(const float* __restrict__ x) {
    extern __shared__ char sm[];
    ushort4*  sIdx = (ushort4*)sm;                 // [1152]  9216B
    float4*   sW   = (float4*)(sm + 9216);         // [1152] 18432B
    uint32_t* tH   = (uint32_t*)(sm + 27648);      // [128*37]
    uint32_t* tL   = (uint32_t*)(sm + 46592);      // [128*37]
    const int tid = threadIdx.x;
    const int p0  = blockIdx.x * 128;
    const int kt  = blockIdx.y;
    const int b   = blockIdx.z;
    const int ck0 = kt * TK_;

    for (int j = tid; j < 1152; j += 256) {
        const int k = j >> 7, pl = j & 127;
        const int gi = (b * 9 + k) * P_ + p0 + pl;
        const float sx = g_sx[gi], sy = g_sy[gi], m = g_mask[gi];
        const float x0f = floorf(sx), y0f = floorf(sy);
        const int x0 = (int)x0f, y0 = (int)y0f;
        const float wx1 = sx - x0f, wy1 = sy - y0f;
        const float wx0 = 1.f - wx1, wy0 = 1.f - wy1;
        const bool vx0 = (x0 >= 0) && (x0 < W_), vx1 = (x0 + 1 >= 0) && (x0 + 1 < W_);
        const bool vy0 = (y0 >= 0) && (y0 < H_), vy1 = (y0 + 1 >= 0) && (y0 + 1 < H_);
        const int cx0 = min(max(x0, 0), W_ - 1), cx1 = min(max(x0 + 1, 0), W_ - 1);
        const int cy0 = min(max(y0, 0), H_ - 1), cy1 = min(max(y0 + 1, 0), H_ - 1);
        ushort4 ii;
        ii.x = (unsigned short)(cy0 * W_ + cx0);
        ii.y = (unsigned short)(cy0 * W_ + cx1);
        ii.z = (unsigned short)(cy1 * W_ + cx0);
        ii.w = (unsigned short)(cy1 * W_ + cx1);
        float4 ww;
        ww.x = wx0 * wy0 * ((vx0 && vy0) ? m : 0.f);
        ww.y = wx1 * wy0 * ((vx1 && vy0) ? m : 0.f);
        ww.z = wx0 * wy1 * ((vx0 && vy1) ? m : 0.f);
        ww.w = wx1 * wy1 * ((vx1 && vy1) ? m : 0.f);
        sIdx[j] = ii;
        sW[j]   = ww;
    }
    __syncthreads();

    const float* xb = x + (size_t)b * C_ * P_;
    __nv_bfloat16* th16 = (__nv_bfloat16*)tH;
    __nv_bfloat16* tl16 = (__nv_bfloat16*)tL;
#pragma unroll 2
    for (int it = 0; it < 32; it++) {
        const int idx = it * 256 + tid;
        const int ck = idx >> 7, pl = idx & 127;
        const int g = ck0 + ck;
        const int c = g / 9;
        const int k = g - c * 9;
        const int j = (k << 7) + pl;
        const ushort4 ii = sIdx[j];
        const float4  ww = sW[j];
        const float* xc = xb + (size_t)c * P_;
        const float v = ww.x * xc[ii.x] + ww.y * xc[ii.y] +
                        ww.z * xc[ii.z] + ww.w * xc[ii.w];
        const __nv_bfloat16 h = __float2bfloat16(v);
        const __nv_bfloat16 l = __float2bfloat16(v - __bfloat162float(h));
        th16[pl * 74 + ck] = h;     // row stride 148B -> conflict-free
        tl16[pl * 74 + ck] = l;
    }
    __syncthreads();

    uint32_t* outH = ((uint32_t*)g_colh) + (((size_t)b * KT_ + kt) * P_ + p0) * 32;
    uint32_t* outL = ((uint32_t*)g_coll) + (((size_t)b * KT_ + kt) * P_ + p0) * 32;
#pragma unroll
    for (int it = 0; it < 16; it++) {
        const int row = it * 8 + (tid >> 5);
        const int col = tid & 31;
        outH[row * 32 + col] = tH[row * 37 + col];
        outL[row * 32 + col] = tL[row * 37 + col];
    }
}

// ---------------- kernel 5: tcgen05 GEMM, bf16 3-term split ------------------
__device__ __forceinline__ void sts128_sw(uint32_t base, int idx, uint4 v) {
    const uint32_t off = (uint32_t)idx * 16u;
    const uint32_t r = off >> 7, o = off & 127u;
    const uint32_t d = base + r * 128u + (o ^ ((r & 7u) << 4));
    asm volatile("st.shared.v4.b32 [%0], {%1,%2,%3,%4};"
                 :: "r"(d), "r"(v.x), "r"(v.y), "r"(v.z), "r"(v.w));
}

__device__ __forceinline__ void load_stage(uint32_t tbase, int kt, int b, int oc0, int p0, int tid) {
    const size_t aoff = ((size_t)kt * OC_ + oc0) * 64;
    const uint4* ah = (const uint4*)(g_wh + aoff);
    const uint4* al = (const uint4*)(g_wl + aoff);
    const size_t boff = (((size_t)b * KT_ + kt) * P_ + p0) * 64;
    const uint4* bh = (const uint4*)(g_colh + boff);
    const uint4* bl = (const uint4*)(g_coll + boff);
#pragma unroll
    for (int i = 0; i < 4; i++) {
        const int idx = tid + i * 256;
        sts128_sw(tbase,         idx, ah[idx]);
        sts128_sw(tbase + 16384, idx, al[idx]);
    }
#pragma unroll
    for (int i = 0; i < 8; i++) {
        const int idx = tid + i * 256;
        sts128_sw(tbase + 32768, idx, bh[idx]);
        sts128_sw(tbase + 65536, idx, bl[idx]);
    }
}

__device__ __forceinline__ void issue_chunk(uint32_t tmem, uint32_t tbase, uint32_t mbar, bool first) {
#if HAS_TC
    asm volatile("fence.proxy.async.shared::cta;" ::: "memory");
    const uint64_t ah = sdesc(tbase);
    const uint64_t al = sdesc(tbase + 16384);
    const uint64_t bh = sdesc(tbase + 32768);
    const uint64_t bl = sdesc(tbase + 65536);
#pragma unroll
    for (int s = 0; s < 4; s++) mma_bf16_ss(tmem, ah + 2 * s, bh + 2 * s, (s == 0 && first) ? 0u : 1u);
#pragma unroll
    for (int s = 0; s < 4; s++) mma_bf16_ss(tmem, ah + 2 * s, bl + 2 * s, 1u);
#pragma unroll
    for (int s = 0; s < 4; s++) mma_bf16_ss(tmem, al + 2 * s, bh + 2 * s, 1u);
    TCGEN05_COMMIT(mbar);
#endif
}

__global__ __launch_bounds__(256, 1) void k_gemm_tc(const float* __restrict__ bias,
                                                    float* __restrict__ out) {
#if HAS_TC
    extern __shared__ char smem[];
    const uint32_t sb = smem_u32(smem);
    const int tid = (int)threadIdx.x;
    const int wid = tid >> 5, lid = tid & 31;
    const int p0  = blockIdx.x * 256;
    const int oc0 = blockIdx.y * 128;
    const int b   = blockIdx.z;
    const uint32_t mb0 = sb + 16, mb1 = sb + 24;
    const uint32_t T0 = sb + 1024;

    if (tid == 0) { MBARRIER_INIT(mb0, 1); MBARRIER_INIT(mb1, 1); }
    if (wid == 0) TCGEN05_ALLOC(sb, 256);
    __syncthreads();
    uint32_t tmem;
    asm volatile("ld.shared.b32 %0, [%1];" : "=r"(tmem) : "r"(sb));

    load_stage(T0, 0, b, oc0, p0, tid);
    __syncthreads();

    int ph0 = 0, ph1 = 0;
    for (int kt = 0; kt < KT_; kt++) {
        const int cur = kt & 1;
        if (wid == 0 && elect1())
            issue_chunk(tmem, T0 + (uint32_t)cur * 98304u, cur ? mb1 : mb0, kt == 0);
        if (kt + 1 < KT_) {
            const int nxt = cur ^ 1;
            if (kt >= 1) {
                if (nxt == 0) { MBARRIER_WAIT_PARITY(mb0, ph0); ph0 ^= 1; }
                else          { MBARRIER_WAIT_PARITY(mb1, ph1); ph1 ^= 1; }
            }
            load_stage(T0 + (uint32_t)nxt * 98304u, kt + 1, b, oc0, p0, tid);
            __syncthreads();
        }
    }
    MBARRIER_WAIT_PARITY(mb0, ph0);
    MBARRIER_WAIT_PARITY(mb1, ph1);
    TCGEN05_FENCE_AFTER();

    // epilogue: 8 warps; subpartition = wid&3 (oc rows), column half = wid>>2
    const int sub = wid & 3, half = wid >> 2;
    const int oc = oc0 + sub * 32 + lid;
    const float bv = bias[oc];
    float* op = out + ((size_t)b * OC_ + oc) * P_ + p0 + half * 128;
#pragma unroll
    for (int j = 0; j < 4; j++) {
        uint32_t r[32];
        TCGEN05_LD_X32(r, tmem + half * 128 + j * 32);
        TCGEN05_WAIT_LD();
#pragma unroll
        for (int c = 0; c < 32; c += 4) {
            float4 v;
            v.x = __uint_as_float(r[c + 0]) + bv;
            v.y = __uint_as_float(r[c + 1]) + bv;
            v.z = __uint_as_float(r[c + 2]) + bv;
            v.w = __uint_as_float(r[c + 3]) + bv;
            *(float4*)(op + j * 32 + c) = v;
        }
    }
    TCGEN05_FENCE_BEFORE();
    __syncthreads();
    if (tid == 0) { MBAR_INVAL(mb0); MBAR_INVAL(mb1); }
    if (wid == 0) { TCGEN05_RELINQ(); TCGEN05_DEALLOC(tmem, 256); }
#endif
}

// ---------------- launch ----------------
extern "C" void kernel_launch(void* const* d_in, const int* in_sizes, int n_in,
                              void* d_out, int out_size) {
    const float* x    = (const float*)d_in[0];
    const float* ow   = (const float*)d_in[1];
    const float* ob   = (const float*)d_in[2];
    const float* wgt  = (const float*)d_in[3];
    const float* bias = (const float*)d_in[4];
    float* out = (float*)d_out;

    cudaFuncSetAttribute(k_gemm_tc,   cudaFuncAttributeMaxDynamicSharedMemorySize, 197632);
    cudaFuncSetAttribute(k_im2col_tc, cudaFuncAttributeMaxDynamicSharedMemorySize, 65536);

    k_offconv<<<dim3((B_ * P_) / 128, NCHUNK), 128>>>(x, ow);
    k_prep<<<(B_ * K_ * P_) / 256, 256>>>(ob);
    k_wsplit<<<(OC_ * CK_) / 256, 256>>>(wgt);
    k_im2col_tc<<<dim3(P_ / 128, KT_, B_), 256, 65536>>>(x);
    k_gemm_tc<<<dim3(P_ / 256, OC_ / 128, B_), 256, 197632>>>(bias, out);
}

// round 4
// speedup vs baseline: 2.6780x; 1.2827x over previous
#include <cuda_runtime.h>
#include <cuda_bf16.h>
#include <cstdint>
#include <cstddef>

// Problem constants
#define B_   4
#define C_   256
#define H_   64
#define W_   64
#define OC_  256
#define K_   9
#define P_   4096          // H*W
#define CK_  2304          // C*K
#define KT_  36            // number of K-chunks of 64 (k-major: kt = k*4 + c/64)
#define TK_  64
#define NCHUNK 4
#define PROW 66            // padded row width (W+2)
#define PN   4356          // (H+2)*(W+2)

// tcgen05 is arch-specific; guard out of the generic compute_103 PTX pass.
#if defined(__CUDA_ARCH_FEAT_SM103_ALL) || defined(__CUDA_ARCH_FEAT_SM100_ALL) || \
    defined(__CUDA_ARCH_FEAT_SM101_ALL) || defined(__CUDA_ARCH_SPECIFIC__) ||     \
    defined(__CUDA_ARCH_FAMILY_SPECIFIC__)
#define HAS_TC 1
#else
#define HAS_TC 0
#endif

// ---------------- scratch (device globals) ----------------
__device__ float g_part[NCHUNK * B_ * 27 * P_];
__device__ float g_sx  [B_ * K_ * P_];
__device__ float g_sy  [B_ * K_ * P_];
__device__ float g_mask[B_ * K_ * P_];
// padded NHWC transpose of x: [b][(py+1)*66+(px+1)][c], zero border
__device__ __align__(16) float g_xtp[(size_t)B_ * PN * 256];
// blocked col buffers: [b][kt][p][64] bf16, 128B K-major rows
__device__ __align__(16) __nv_bfloat16 g_colh[(size_t)B_ * KT_ * P_ * TK_];
__device__ __align__(16) __nv_bfloat16 g_coll[(size_t)B_ * KT_ * P_ * TK_];
// blocked weights: [kt][oc][64] bf16 (k-major kt)
__device__ __align__(16) __nv_bfloat16 g_wh[(size_t)KT_ * OC_ * TK_];
__device__ __align__(16) __nv_bfloat16 g_wl[(size_t)KT_ * OC_ * TK_];

// ==================== PTX helpers ====================
__device__ __forceinline__ uint32_t smem_u32(const void* p) {
    uint32_t a;
    asm("{ .reg .u64 t; cvta.to.shared.u64 t, %1; cvt.u32.u64 %0, t; }" : "=r"(a) : "l"(p));
    return a;
}
__device__ __forceinline__ uint32_t elect1() {
    uint32_t p;
    asm volatile("{\n .reg .pred p;\n elect.sync _|p, 0xFFFFFFFF;\n selp.b32 %0,1,0,p;\n}" : "=r"(p));
    return p;
}
#define MBARRIER_INIT(addr, cnt) \
    asm volatile("mbarrier.init.shared.b64 [%0], %1;" :: "r"(addr), "r"((uint32_t)(cnt)) : "memory")
#define MBAR_INVAL(addr) \
    asm volatile("mbarrier.inval.shared.b64 [%0];" :: "r"(addr) : "memory")
#define MBARRIER_WAIT_PARITY(mbar, par) do {                                   \
    uint32_t _m = (mbar); uint32_t _p = (uint32_t)(par); uint32_t _d;          \
    asm volatile("{\n .reg .pred p;\n"                                         \
        " mbarrier.try_wait.parity.acquire.cta.shared::cta.b64 p, [%1], %2;\n" \
        " selp.b32 %0, 1, 0, p;\n}" : "=r"(_d) : "r"(_m), "r"(_p) : "memory"); \
    if (!_d) {                                                                 \
        asm volatile("{\n .reg .pred P1;\n"                                    \
            "WL_%=:\n"                                                         \
            " mbarrier.try_wait.parity.acquire.cta.shared::cta.b64 P1, [%0], %1, 0x989680;\n" \
            " @P1 bra.uni WD_%=;\n bra.uni WL_%=;\nWD_%=:\n}"                  \
            :: "r"(_m), "r"(_p) : "memory");                                   \
    }                                                                          \
} while (0)

#if HAS_TC
#define TCGEN05_ALLOC(sa, n) \
    asm volatile("tcgen05.alloc.cta_group::1.sync.aligned.shared::cta.b32 [%0], %1;" \
        :: "r"((uint32_t)(sa)), "r"((uint32_t)(n)) : "memory")
#define TCGEN05_DEALLOC(t, n) \
    asm volatile("tcgen05.dealloc.cta_group::1.sync.aligned.b32 %0, %1;" :: "r"(t), "r"((uint32_t)(n)))
#define TCGEN05_RELINQ() \
    asm volatile("tcgen05.relinquish_alloc_permit.cta_group::1.sync.aligned;")
#define TCGEN05_COMMIT(mbar) \
    asm volatile("tcgen05.commit.cta_group::1.mbarrier::arrive::one.shared::cluster.b64 [%0];" \
        :: "r"((uint32_t)(mbar)) : "memory")
#define TCGEN05_FENCE_AFTER()  asm volatile("tcgen05.fence::after_thread_sync;" ::: "memory")
#define TCGEN05_FENCE_BEFORE() asm volatile("tcgen05.fence::before_thread_sync;" ::: "memory")
#define TCGEN05_WAIT_LD()      asm volatile("tcgen05.wait::ld.sync.aligned;" ::: "memory")
#define TCGEN05_LD_X32(r, ta) \
    asm volatile("tcgen05.ld.sync.aligned.32x32b.x32.b32 " \
        "{%0,%1,%2,%3,%4,%5,%6,%7,%8,%9,%10,%11,%12,%13,%14,%15," \
        "%16,%17,%18,%19,%20,%21,%22,%23,%24,%25,%26,%27,%28,%29,%30,%31}, [%32];" \
        : "=r"((r)[0]),"=r"((r)[1]),"=r"((r)[2]),"=r"((r)[3]),"=r"((r)[4]),"=r"((r)[5]),"=r"((r)[6]),"=r"((r)[7]), \
          "=r"((r)[8]),"=r"((r)[9]),"=r"((r)[10]),"=r"((r)[11]),"=r"((r)[12]),"=r"((r)[13]),"=r"((r)[14]),"=r"((r)[15]), \
          "=r"((r)[16]),"=r"((r)[17]),"=r"((r)[18]),"=r"((r)[19]),"=r"((r)[20]),"=r"((r)[21]),"=r"((r)[22]),"=r"((r)[23]), \
          "=r"((r)[24]),"=r"((r)[25]),"=r"((r)[26]),"=r"((r)[27]),"=r"((r)[28]),"=r"((r)[29]),"=r"((r)[30]),"=r"((r)[31]) \
        : "r"(ta))
#endif

// SW128 K-major descriptor (layout=2, version=1, SBO=64, LBO=1)
__device__ __forceinline__ uint64_t sdesc(uint32_t addr) {
    return 0x4000404000010000ull | (uint64_t)((addr >> 4) & 0x3FFF);
}
// idesc: D=f32, A=bf16, B=bf16, N=256, M=128, K-major both
#define IDESC_ 0x8400490u

__device__ __forceinline__ void mma_bf16_ss(uint32_t d, uint64_t ad, uint64_t bd, uint32_t en) {
#if HAS_TC
    asm volatile("{\n .reg .pred p;\n setp.ne.u32 p, %5, 0;\n"
        " tcgen05.mma.cta_group::1.kind::f16 [%0], %1, %2, %3, {%4,%4,%4,%4}, p;\n}"
        :: "r"(d), "l"(ad), "l"(bd), "r"(IDESC_), "r"(0u), "r"(en) : "memory");
#endif
}

// ---------------- kernel 0a: zero padded transpose buffer --------------------
__global__ __launch_bounds__(256) void k_zero_xtp() {
    const size_t i = (size_t)blockIdx.x * 256 + threadIdx.x;   // over PN*256 float4s
    ((float4*)g_xtp)[i] = make_float4(0.f, 0.f, 0.f, 0.f);
}

// ---------------- kernel 0b: NCHW -> padded NHWC transpose -------------------
__global__ __launch_bounds__(256) void k_transpose(const float* __restrict__ x) {
    __shared__ float s[64][129];
    const int py = blockIdx.x;       // 0..63
    const int c0 = blockIdx.y * 128; // 0 or 128
    const int b  = blockIdx.z;
    const int tid = threadIdx.x;

    const float* xb = x + ((size_t)b * C_ + c0) * P_ + py * 64;
    const int px = tid & 63;
    const int cb = tid >> 6;
#pragma unroll
    for (int it = 0; it < 32; it++) {
        const int c = it * 4 + cb;
        s[px][c] = xb[(size_t)c * P_ + px];
    }
    __syncthreads();

    float* ob = g_xtp + (size_t)b * PN * 256;
#pragma unroll
    for (int it = 0; it < 32; it++) {
        const int idx = it * 256 + tid;
        const int pxo = idx >> 7;
        const int c   = idx & 127;
        ob[((size_t)(py + 1) * PROW + pxo + 1) * 256 + c0 + c] = s[pxo][c];
    }
}

// ---------------- kernel 1: offset-predictor conv (27ch, 3x3, pad1) ----------
__global__ __launch_bounds__(128) void k_offconv(const float* __restrict__ x,
                                                 const float* __restrict__ ow) {
    const int tid  = threadIdx.x;
    const int gpix = blockIdx.x * 128 + tid;
    const int b  = gpix >> 12;
    const int p  = gpix & (P_ - 1);
    const int py = p >> 6;
    const int px = p & 63;
    const int c0 = blockIdx.y * (C_ / NCHUNK);

    __shared__ float ws[27 * 12];

    float acc[27];
#pragma unroll
    for (int i = 0; i < 27; i++) acc[i] = 0.f;

    const float* xb = x + (size_t)b * C_ * P_;

    for (int cc = 0; cc < C_ / NCHUNK; cc++) {
        const int c = c0 + cc;
        __syncthreads();
        for (int i = tid; i < 243; i += 128) {
            int ch = i / 9, t = i - ch * 9;
            ws[ch * 12 + t] = ow[ch * CK_ + c * 9 + t];
        }
        __syncthreads();

        float xv[9];
        const float* xc = xb + (size_t)c * P_;
#pragma unroll
        for (int ky = 0; ky < 3; ky++) {
            const int yy = py + ky - 1;
            const bool yok = ((unsigned)yy < (unsigned)H_);
#pragma unroll
            for (int kx = 0; kx < 3; kx++) {
                const int xx = px + kx - 1;
                const bool ok = yok && ((unsigned)xx < (unsigned)W_);
                xv[ky * 3 + kx] = ok ? xc[yy * W_ + xx] : 0.f;
            }
        }
#pragma unroll
        for (int ch = 0; ch < 27; ch++) {
            const float* wp = &ws[ch * 12];
            float s = acc[ch];
#pragma unroll
            for (int t = 0; t < 9; t++) s += xv[t] * wp[t];
            acc[ch] = s;
        }
    }

    const size_t base = (((size_t)blockIdx.y * B_ + b) * 27) * P_ + p;
#pragma unroll
    for (int ch = 0; ch < 27; ch++) g_part[base + (size_t)ch * P_] = acc[ch];
}

// ---------------- kernel 2: reduce chunks, add bias, build sx/sy/mask --------
__global__ __launch_bounds__(256) void k_prep(const float* __restrict__ ob) {
    const int idx = blockIdx.x * 256 + threadIdx.x;
    if (idx >= B_ * K_ * P_) return;
    const int p  = idx & (P_ - 1);
    const int bk = idx >> 12;
    const int b  = bk / K_;
    const int k  = bk - b * K_;

    float ox = 0.f, oy = 0.f, om = 0.f;
#pragma unroll
    for (int ch = 0; ch < NCHUNK; ch++) {
        const size_t base = (((size_t)ch * B_ + b) * 27) * P_ + p;
        ox += g_part[base + (size_t)k * P_];
        oy += g_part[base + (size_t)(9 + k) * P_];
        om += g_part[base + (size_t)(18 + k) * P_];
    }
    ox += ob[k];
    oy += ob[9 + k];
    om += ob[18 + k];

    const int py = p >> 6, px = p & 63;
    const int kx = k % 3, ky = k / 3;

    g_sx[idx]   = (float)(px - 1 + (kx - 1)) + ox;
    g_sy[idx]   = (float)(py - 1 + (ky - 1)) + oy;
    g_mask[idx] = 1.f / (1.f + expf(-om));
}

// ---------------- kernel 3: weight split, k-major blocked --------------------
__global__ __launch_bounds__(256) void k_wsplit(const float* __restrict__ w) {
    const int idx = blockIdx.x * 256 + threadIdx.x;  // < OC_*CK_
    const int oc  = idx / CK_;
    const int rem = idx - oc * CK_;
    const int c = rem / 9, k = rem - c * 9;
    const int kt = k * 4 + (c >> 6);       // k-major K-order
    const int ck = c & 63;
    const float v = w[idx];
    const __nv_bfloat16 h = __float2bfloat16(v);
    const __nv_bfloat16 l = __float2bfloat16(v - __bfloat162float(h));
    const size_t o = ((size_t)kt * OC_ + oc) * 64 + ck;
    g_wh[o] = h;
    g_wl[o] = l;
}

// ---------------- kernel 4: coalesced bilinear im2col (NHWC gather) ----------
// block: (p-tile 128, kt, b). kt = k*4 + cchunk. Stage1: per-pixel corner
// offsets+weights into smem. Stage2: float2 coalesced gathers over channels.
__global__ __launch_bounds__(256) void k_im2col_tc() {
    __shared__ uint32_t sOff[4][128];
    __shared__ float    sWgt[4][128];
    const int tid = threadIdx.x;
    const int p0  = blockIdx.x * 128;
    const int kt  = blockIdx.y;
    const int b   = blockIdx.z;
    const int k   = kt >> 2;
    const int c0  = (kt & 3) << 6;

    if (tid < 128) {
        const int gi = (b * 9 + k) * P_ + p0 + tid;
        const float sx = g_sx[gi], sy = g_sy[gi], m = g_mask[gi];
        const float x0f = floorf(sx), y0f = floorf(sy);
        const int x0 = (int)x0f, y0 = (int)y0f;
        const float wx1 = sx - x0f, wy1 = sy - y0f;
        const float wx0 = 1.f - wx1, wy0 = 1.f - wy1;
        const bool vx0 = (x0 >= 0) && (x0 < W_), vx1 = (x0 + 1 >= 0) && (x0 + 1 < W_);
        const bool vy0 = (y0 >= 0) && (y0 < H_), vy1 = (y0 + 1 >= 0) && (y0 + 1 < H_);
        const int cx0 = min(max(x0, 0), W_ - 1), cx1 = min(max(x0 + 1, 0), W_ - 1);
        const int cy0 = min(max(y0, 0), H_ - 1), cy1 = min(max(y0 + 1, 0), H_ - 1);
        // padded-buffer rows at clamped coords; invalid corners zeroed by weight
        sOff[0][tid] = (uint32_t)((((cy0 + 1) * PROW + cx0 + 1) * 256 + c0) * 4);
        sOff[1][tid] = (uint32_t)((((cy0 + 1) * PROW + cx1 + 1) * 256 + c0) * 4);
        sOff[2][tid] = (uint32_t)((((cy1 + 1) * PROW + cx0 + 1) * 256 + c0) * 4);
        sOff[3][tid] = (uint32_t)((((cy1 + 1) * PROW + cx1 + 1) * 256 + c0) * 4);
        sWgt[0][tid] = wx0 * wy0 * ((vx0 && vy0) ? m : 0.f);
        sWgt[1][tid] = wx1 * wy0 * ((vx1 && vy0) ? m : 0.f);
        sWgt[2][tid] = wx0 * wy1 * ((vx0 && vy1) ? m : 0.f);
        sWgt[3][tid] = wx1 * wy1 * ((vx1 && vy1) ? m : 0.f);
    }
    __syncthreads();

    const char* xb = (const char*)(g_xtp + (size_t)b * PN * 256);
    const int cp = tid & 31;                 // channel pair 0..31
    uint32_t* oh = (uint32_t*)g_colh + (((size_t)b * KT_ + kt) * P_ + p0) * 32 + cp;
    uint32_t* ol = (uint32_t*)g_coll + (((size_t)b * KT_ + kt) * P_ + p0) * 32 + cp;

#pragma unroll
    for (int it = 0; it < 16; it++) {
        const int pl = it * 8 + (tid >> 5);
        const uint32_t cb = (uint32_t)cp * 8u;
        const float2 a0 = *(const float2*)(xb + sOff[0][pl] + cb);
        const float2 a1 = *(const float2*)(xb + sOff[1][pl] + cb);
        const float2 a2 = *(const float2*)(xb + sOff[2][pl] + cb);
        const float2 a3 = *(const float2*)(xb + sOff[3][pl] + cb);
        const float w0 = sWgt[0][pl], w1 = sWgt[1][pl], w2 = sWgt[2][pl], w3 = sWgt[3][pl];
        const float v0 = w0 * a0.x + w1 * a1.x + w2 * a2.x + w3 * a3.x;
        const float v1 = w0 * a0.y + w1 * a1.y + w2 * a2.y + w3 * a3.y;
        const __nv_bfloat16 h0 = __float2bfloat16(v0);
        const __nv_bfloat16 h1 = __float2bfloat16(v1);
        __nv_bfloat162 hh; hh.x = h0; hh.y = h1;
        __nv_bfloat162 ll;
        ll.x = __float2bfloat16(v0 - __bfloat162float(h0));
        ll.y = __float2bfloat16(v1 - __bfloat162float(h1));
        oh[(size_t)pl * 32] = *(const uint32_t*)&hh;
        ol[(size_t)pl * 32] = *(const uint32_t*)&ll;
    }
}

// ---------------- kernel 5: tcgen05 GEMM, bf16 3-term split ------------------
__device__ __forceinline__ void sts128_sw(uint32_t base, int idx, uint4 v) {
    const uint32_t off = (uint32_t)idx * 16u;
    const uint32_t r = off >> 7, o = off & 127u;
    const uint32_t d = base + r * 128u + (o ^ ((r & 7u) << 4));
    asm volatile("st.shared.v4.b32 [%0], {%1,%2,%3,%4};"
                 :: "r"(d), "r"(v.x), "r"(v.y), "r"(v.z), "r"(v.w));
}

__device__ __forceinline__ void load_stage(uint32_t tbase, int kt, int b, int oc0, int p0, int tid) {
    const size_t aoff = ((size_t)kt * OC_ + oc0) * 64;
    const uint4* ah = (const uint4*)(g_wh + aoff);
    const uint4* al = (const uint4*)(g_wl + aoff);
    const size_t boff = (((size_t)b * KT_ + kt) * P_ + p0) * 64;
    const uint4* bh = (const uint4*)(g_colh + boff);
    const uint4* bl = (const uint4*)(g_coll + boff);
#pragma unroll
    for (int i = 0; i < 4; i++) {
        const int idx = tid + i * 256;
        sts128_sw(tbase,         idx, ah[idx]);
        sts128_sw(tbase + 16384, idx, al[idx]);
    }
#pragma unroll
    for (int i = 0; i < 8; i++) {
        const int idx = tid + i * 256;
        sts128_sw(tbase + 32768, idx, bh[idx]);
        sts128_sw(tbase + 65536, idx, bl[idx]);
    }
}

__device__ __forceinline__ void issue_chunk(uint32_t tmem, uint32_t tbase, uint32_t mbar, bool first) {
#if HAS_TC
    asm volatile("fence.proxy.async.shared::cta;" ::: "memory");
    const uint64_t ah = sdesc(tbase);
    const uint64_t al = sdesc(tbase + 16384);
    const uint64_t bh = sdesc(tbase + 32768);
    const uint64_t bl = sdesc(tbase + 65536);
#pragma unroll
    for (int s = 0; s < 4; s++) mma_bf16_ss(tmem, ah + 2 * s, bh + 2 * s, (s == 0 && first) ? 0u : 1u);
#pragma unroll
    for (int s = 0; s < 4; s++) mma_bf16_ss(tmem, ah + 2 * s, bl + 2 * s, 1u);
#pragma unroll
    for (int s = 0; s < 4; s++) mma_bf16_ss(tmem, al + 2 * s, bh + 2 * s, 1u);
    TCGEN05_COMMIT(mbar);
#endif
}

__global__ __launch_bounds__(256, 1) void k_gemm_tc(const float* __restrict__ bias,
                                                    float* __restrict__ out) {
#if HAS_TC
    extern __shared__ char smem[];
    const uint32_t sb = smem_u32(smem);
    const int tid = (int)threadIdx.x;
    const int wid = tid >> 5, lid = tid & 31;
    const int p0  = blockIdx.x * 256;
    const int oc0 = blockIdx.y * 128;
    const int b   = blockIdx.z;
    const uint32_t mb0 = sb + 16, mb1 = sb + 24;
    const uint32_t T0 = sb + 1024;

    if (tid == 0) { MBARRIER_INIT(mb0, 1); MBARRIER_INIT(mb1, 1); }
    if (wid == 0) TCGEN05_ALLOC(sb, 256);
    __syncthreads();
    uint32_t tmem;
    asm volatile("ld.shared.b32 %0, [%1];" : "=r"(tmem) : "r"(sb));

    load_stage(T0, 0, b, oc0, p0, tid);
    __syncthreads();

    int ph0 = 0, ph1 = 0;
    for (int kt = 0; kt < KT_; kt++) {
        const int cur = kt & 1;
        if (wid == 0 && elect1())
            issue_chunk(tmem, T0 + (uint32_t)cur * 98304u, cur ? mb1 : mb0, kt == 0);
        if (kt + 1 < KT_) {
            const int nxt = cur ^ 1;
            if (kt >= 1) {
                if (nxt == 0) { MBARRIER_WAIT_PARITY(mb0, ph0); ph0 ^= 1; }
                else          { MBARRIER_WAIT_PARITY(mb1, ph1); ph1 ^= 1; }
            }
            load_stage(T0 + (uint32_t)nxt * 98304u, kt + 1, b, oc0, p0, tid);
            __syncthreads();
        }
    }
    MBARRIER_WAIT_PARITY(mb0, ph0);
    MBARRIER_WAIT_PARITY(mb1, ph1);
    TCGEN05_FENCE_AFTER();

    // epilogue: 8 warps; subpartition = wid&3 (oc rows), column half = wid>>2
    const int sub = wid & 3, half = wid >> 2;
    const int oc = oc0 + sub * 32 + lid;
    const float bv = bias[oc];
    float* op = out + ((size_t)b * OC_ + oc) * P_ + p0 + half * 128;
#pragma unroll
    for (int j = 0; j < 4; j++) {
        uint32_t r[32];
        TCGEN05_LD_X32(r, tmem + half * 128 + j * 32);
        TCGEN05_WAIT_LD();
#pragma unroll
        for (int c = 0; c < 32; c += 4) {
            float4 v;
            v.x = __uint_as_float(r[c + 0]) + bv;
            v.y = __uint_as_float(r[c + 1]) + bv;
            v.z = __uint_as_float(r[c + 2]) + bv;
            v.w = __uint_as_float(r[c + 3]) + bv;
            *(float4*)(op + j * 32 + c) = v;
        }
    }
    TCGEN05_FENCE_BEFORE();
    __syncthreads();
    if (tid == 0) { MBAR_INVAL(mb0); MBAR_INVAL(mb1); }
    if (wid == 0) { TCGEN05_RELINQ(); TCGEN05_DEALLOC(tmem, 256); }
#endif
}

// ---------------- launch ----------------
extern "C" void kernel_launch(void* const* d_in, const int* in_sizes, int n_in,
                              void* d_out, int out_size) {
    const float* x    = (const float*)d_in[0];
    const float* ow   = (const float*)d_in[1];
    const float* ob   = (const float*)d_in[2];
    const float* wgt  = (const float*)d_in[3];
    const float* bias = (const float*)d_in[4];
    float* out = (float*)d_out;

    cudaFuncSetAttribute(k_gemm_tc, cudaFuncAttributeMaxDynamicSharedMemorySize, 197632);

    k_zero_xtp<<<PN, 256>>>();                       // PN*256 float4 = whole buffer
    k_transpose<<<dim3(64, 2, B_), 256>>>(x);
    k_offconv<<<dim3((B_ * P_) / 128, NCHUNK), 128>>>(x, ow);
    k_prep<<<(B_ * K_ * P_) / 256, 256>>>(ob);
    k_wsplit<<<(OC_ * CK_) / 256, 256>>>(wgt);
    k_im2col_tc<<<dim3(P_ / 128, KT_, B_), 256>>>();
    k_gemm_tc<<<dim3(P_ / 256, OC_ / 128, B_), 256, 197632>>>(bias, out);
}

// round 5
// speedup vs baseline: 3.2123x; 1.1995x over previous
#include <cuda_runtime.h>
#include <cuda_bf16.h>
#include <cstdint>
#include <cstddef>

// Problem constants
#define B_   4
#define C_   256
#define H_   64
#define W_   64
#define OC_  256
#define K_   9
#define P_   4096          // H*W
#define CK_  2304          // C*K
#define KT_  36            // K-chunks of 64 (k-major: kt = k*4 + c/64)
#define TK_  64
#define PROW 66            // padded row width (W+2)
#define PN   4356          // (H+2)*(W+2)

// tcgen05 is arch-specific; guard out of the generic compute_103 PTX pass.
#if defined(__CUDA_ARCH_FEAT_SM103_ALL) || defined(__CUDA_ARCH_FEAT_SM100_ALL) || \
    defined(__CUDA_ARCH_FEAT_SM101_ALL) || defined(__CUDA_ARCH_SPECIFIC__) ||     \
    defined(__CUDA_ARCH_FAMILY_SPECIFIC__)
#define HAS_TC 1
#else
#define HAS_TC 0
#endif

// ---------------- scratch (device globals) ----------------
__device__ float g_sx  [B_ * K_ * P_];
__device__ float g_sy  [B_ * K_ * P_];
__device__ float g_mask[B_ * K_ * P_];
// padded NHWC transpose of x: [b][(py+1)*66+(px+1)][c], zero border
__device__ __align__(16) float g_xtp[(size_t)B_ * PN * 256];
// blocked col buffers: [b][kt][p][64] bf16, 128B K-major rows
__device__ __align__(16) __nv_bfloat16 g_colh[(size_t)B_ * KT_ * P_ * TK_];
__device__ __align__(16) __nv_bfloat16 g_coll[(size_t)B_ * KT_ * P_ * TK_];
// blocked main weights: [kt][oc][64] bf16 (k-major kt)
__device__ __align__(16) __nv_bfloat16 g_wh[(size_t)KT_ * OC_ * TK_];
__device__ __align__(16) __nv_bfloat16 g_wl[(size_t)KT_ * OC_ * TK_];
// blocked offset-conv weights: [kt][32 (27 padded)][64] bf16
__device__ __align__(16) __nv_bfloat16 g_owh[(size_t)KT_ * 32 * TK_];
__device__ __align__(16) __nv_bfloat16 g_owl[(size_t)KT_ * 32 * TK_];

// ==================== PTX helpers ====================
__device__ __forceinline__ uint32_t smem_u32(const void* p) {
    uint32_t a;
    asm("{ .reg .u64 t; cvta.to.shared.u64 t, %1; cvt.u32.u64 %0, t; }" : "=r"(a) : "l"(p));
    return a;
}
__device__ __forceinline__ uint32_t elect1() {
    uint32_t p;
    asm volatile("{\n .reg .pred p;\n elect.sync _|p, 0xFFFFFFFF;\n selp.b32 %0,1,0,p;\n}" : "=r"(p));
    return p;
}
#define MBARRIER_INIT(addr, cnt) \
    asm volatile("mbarrier.init.shared.b64 [%0], %1;" :: "r"(addr), "r"((uint32_t)(cnt)) : "memory")
#define MBAR_INVAL(addr) \
    asm volatile("mbarrier.inval.shared.b64 [%0];" :: "r"(addr) : "memory")
#define MBARRIER_WAIT_PARITY(mbar, par) do {                                   \
    uint32_t _m = (mbar); uint32_t _p = (uint32_t)(par); uint32_t _d;          \
    asm volatile("{\n .reg .pred p;\n"                                         \
        " mbarrier.try_wait.parity.acquire.cta.shared::cta.b64 p, [%1], %2;\n" \
        " selp.b32 %0, 1, 0, p;\n}" : "=r"(_d) : "r"(_m), "r"(_p) : "memory"); \
    if (!_d) {                                                                 \
        asm volatile("{\n .reg .pred P1;\n"                                    \
            "WL_%=:\n"                                                         \
            " mbarrier.try_wait.parity.acquire.cta.shared::cta.b64 P1, [%0], %1, 0x989680;\n" \
            " @P1 bra.uni WD_%=;\n bra.uni WL_%=;\nWD_%=:\n}"                  \
            :: "r"(_m), "r"(_p) : "memory");                                   \
    }                                                                          \
} while (0)
#define CP_COMMIT() asm volatile("cp.async.commit_group;" ::: "memory")
#define CP_WAIT0()  asm volatile("cp.async.wait_group 0;" ::: "memory")

#if HAS_TC
#define TCGEN05_ALLOC(sa, n) \
    asm volatile("tcgen05.alloc.cta_group::1.sync.aligned.shared::cta.b32 [%0], %1;" \
        :: "r"((uint32_t)(sa)), "r"((uint32_t)(n)) : "memory")
#define TCGEN05_DEALLOC(t, n) \
    asm volatile("tcgen05.dealloc.cta_group::1.sync.aligned.b32 %0, %1;" :: "r"(t), "r"((uint32_t)(n)))
#define TCGEN05_RELINQ() \
    asm volatile("tcgen05.relinquish_alloc_permit.cta_group::1.sync.aligned;")
#define TCGEN05_COMMIT(mbar) \
    asm volatile("tcgen05.commit.cta_group::1.mbarrier::arrive::one.shared::cluster.b64 [%0];" \
        :: "r"((uint32_t)(mbar)) : "memory")
#define TCGEN05_FENCE_AFTER()  asm volatile("tcgen05.fence::after_thread_sync;" ::: "memory")
#define TCGEN05_FENCE_BEFORE() asm volatile("tcgen05.fence::before_thread_sync;" ::: "memory")
#define TCGEN05_WAIT_LD()      asm volatile("tcgen05.wait::ld.sync.aligned;" ::: "memory")
#define TCGEN05_LD_X32(r, ta) \
    asm volatile("tcgen05.ld.sync.aligned.32x32b.x32.b32 " \
        "{%0,%1,%2,%3,%4,%5,%6,%7,%8,%9,%10,%11,%12,%13,%14,%15," \
        "%16,%17,%18,%19,%20,%21,%22,%23,%24,%25,%26,%27,%28,%29,%30,%31}, [%32];" \
        : "=r"((r)[0]),"=r"((r)[1]),"=r"((r)[2]),"=r"((r)[3]),"=r"((r)[4]),"=r"((r)[5]),"=r"((r)[6]),"=r"((r)[7]), \
          "=r"((r)[8]),"=r"((r)[9]),"=r"((r)[10]),"=r"((r)[11]),"=r"((r)[12]),"=r"((r)[13]),"=r"((r)[14]),"=r"((r)[15]), \
          "=r"((r)[16]),"=r"((r)[17]),"=r"((r)[18]),"=r"((r)[19]),"=r"((r)[20]),"=r"((r)[21]),"=r"((r)[22]),"=r"((r)[23]), \
          "=r"((r)[24]),"=r"((r)[25]),"=r"((r)[26]),"=r"((r)[27]),"=r"((r)[28]),"=r"((r)[29]),"=r"((r)[30]),"=r"((r)[31]) \
        : "r"(ta))
#endif

// SW128 K-major descriptor (layout=2, version=1, SBO=64, LBO=1)
__device__ __forceinline__ uint64_t sdesc(uint32_t addr) {
    return 0x4000404000010000ull | (uint64_t)((addr >> 4) & 0x3FFF);
}
// idesc kind::f16 bf16/f32: M=128 with N=256 / N=32
#define IDESC256_ 0x8400490u
#define IDESC32_  0x8080490u

__device__ __forceinline__ void mma_bf16_ss(uint32_t d, uint64_t ad, uint64_t bd,
                                            uint32_t idesc, uint32_t en) {
#if HAS_TC
    asm volatile("{\n .reg .pred p;\n setp.ne.u32 p, %5, 0;\n"
        " tcgen05.mma.cta_group::1.kind::f16 [%0], %1, %2, %3, {%4,%4,%4,%4}, p;\n}"
        :: "r"(d), "l"(ad), "l"(bd), "r"(idesc), "r"(0u), "r"(en) : "memory");
#endif
}

// ---------------- kernel 0a: zero xtp border only ----------------------------
__global__ __launch_bounds__(64) void k_zero_border() {
    const int pos = blockIdx.x;      // 0..259
    const int b   = blockIdx.y;
    int row, col;
    if (pos < 66)       { row = 0;  col = pos; }
    else if (pos < 132) { row = 65; col = pos - 66; }
    else if (pos < 196) { row = pos - 132 + 1; col = 0; }
    else                { row = pos - 196 + 1; col = 65; }
    float4* dst = (float4*)(g_xtp + ((size_t)b * PN + row * PROW + col) * 256);
    dst[threadIdx.x] = make_float4(0.f, 0.f, 0.f, 0.f);
}

// ---------------- kernel 0b: NCHW -> padded NHWC transpose -------------------
__global__ __launch_bounds__(256) void k_transpose(const float* __restrict__ x) {
    __shared__ float s[64][129];
    const int py = blockIdx.x;
    const int c0 = blockIdx.y * 128;
    const int b  = blockIdx.z;
    const int tid = threadIdx.x;

    const float* xb = x + ((size_t)b * C_ + c0) * P_ + py * 64;
    const int px = tid & 63;
    const int cb = tid >> 6;
#pragma unroll
    for (int it = 0; it < 32; it++) {
        const int c = it * 4 + cb;
        s[px][c] = xb[(size_t)c * P_ + px];
    }
    __syncthreads();

    float* ob = g_xtp + (size_t)b * PN * 256;
#pragma unroll
    for (int it = 0; it < 32; it++) {
        const int idx = it * 256 + tid;
        const int pxo = idx >> 7;
        const int c   = idx & 127;
        ob[((size_t)(py + 1) * PROW + pxo + 1) * 256 + c0 + c] = s[pxo][c];
    }
}

// ---------------- kernel 1: main weight split, k-major blocked ---------------
__global__ __launch_bounds__(256) void k_wsplit(const float* __restrict__ w) {
    const int idx = blockIdx.x * 256 + threadIdx.x;
    const int oc  = idx / CK_;
    const int rem = idx - oc * CK_;
    const int c = rem / 9, k = rem - c * 9;
    const int kt = k * 4 + (c >> 6);
    const int ck = c & 63;
    const float v = w[idx];
    const __nv_bfloat16 h = __float2bfloat16(v);
    const __nv_bfloat16 l = __float2bfloat16(v - __bfloat162float(h));
    const size_t o = ((size_t)kt * OC_ + oc) * 64 + ck;
    g_wh[o] = h;
    g_wl[o] = l;
}

// ---------------- kernel 2: offset weight split, blocked [kt][32][64] --------
__global__ __launch_bounds__(256) void k_woffsplit(const float* __restrict__ ow) {
    const int idx = blockIdx.x * 256 + threadIdx.x;  // < 36*32*64
    const int kt = idx >> 11;
    const int n  = (idx >> 6) & 31;
    const int ck = idx & 63;
    const int k  = kt >> 2;
    const int c  = ((kt & 3) << 6) + ck;
    const float v = (n < 27) ? ow[(size_t)n * CK_ + c * 9 + k] : 0.f;
    const __nv_bfloat16 h = __float2bfloat16(v);
    const __nv_bfloat16 l = __float2bfloat16(v - __bfloat162float(h));
    g_owh[idx] = h;
    g_owl[idx] = l;
}

// ---------------- swizzled 16B / 8B smem stores -------------------------------
__device__ __forceinline__ void sts128_sw(uint32_t base, int idx, uint4 v) {
    const uint32_t off = (uint32_t)idx * 16u;
    const uint32_t r = off >> 7, o = off & 127u;
    const uint32_t d = base + r * 128u + (o ^ ((r & 7u) << 4));
    asm volatile("st.shared.v4.b32 [%0], {%1,%2,%3,%4};"
                 :: "r"(d), "r"(v.x), "r"(v.y), "r"(v.z), "r"(v.w));
}
__device__ __forceinline__ void cpasync16_sw(uint32_t base, int idx, const void* src) {
    const uint32_t off = (uint32_t)idx * 16u;
    const uint32_t r = off >> 7, o = off & 127u;
    const uint32_t d = base + r * 128u + (o ^ ((r & 7u) << 4));
    asm volatile("cp.async.cg.shared.global [%0], [%1], 16;" :: "r"(d), "l"(src));
}

// ---------------- kernel 3: offset-predictor conv on tcgen05 ------------------
// D[128 p, 32 ch] += plain_im2col[128 p, 64ck] * Woff[32, 64ck]^T over 36 chunks.
// Epilogue computes sx/sy/mask directly (replaces old k_offconv + k_prep).
// Stage layout: Ah 16K | Al 16K | Bh 4K | Bl 4K = 40960 B; two stages.
#define OFF_STG 40960u

__device__ __forceinline__ void build_off_stage(uint32_t tbase, int kt, int b, int p0, int tid) {
    const int k  = kt >> 2;
    const int c0 = (kt & 3) << 6;
    const int ky = k / 3, kx = k - ky * 3;
    const float* xb = g_xtp + (size_t)b * PN * 256;
    const int j  = tid & 15;     // float4 within 64-ch row
    const int r0 = tid >> 4;     // 0..7
#pragma unroll
    for (int it = 0; it < 16; it++) {
        const int row = it * 8 + r0;
        const int p = p0 + row;
        const int py = p >> 6, px = p & 63;
        const float4 v = *(const float4*)(xb + ((size_t)(py + ky) * PROW + (px + kx)) * 256 + c0 + j * 4);
        __nv_bfloat162 h0, h1, l0, l1;
        h0.x = __float2bfloat16(v.x); h0.y = __float2bfloat16(v.y);
        h1.x = __float2bfloat16(v.z); h1.y = __float2bfloat16(v.w);
        l0.x = __float2bfloat16(v.x - __bfloat162float(h0.x));
        l0.y = __float2bfloat16(v.y - __bfloat162float(h0.y));
        l1.x = __float2bfloat16(v.z - __bfloat162float(h1.x));
        l1.y = __float2bfloat16(v.w - __bfloat162float(h1.y));
        const uint32_t o = (uint32_t)j * 8u;
        const uint32_t d = tbase + (uint32_t)row * 128u + (o ^ (((uint32_t)row & 7u) << 4));
        asm volatile("st.shared.v2.b32 [%0], {%1,%2};"
                     :: "r"(d), "r"(*(uint32_t*)&h0), "r"(*(uint32_t*)&h1));
        asm volatile("st.shared.v2.b32 [%0], {%1,%2};"
                     :: "r"(d + 16384u), "r"(*(uint32_t*)&l0), "r"(*(uint32_t*)&l1));
    }
    const uint4* bh = (const uint4*)(g_owh + (size_t)kt * 32 * 64);
    const uint4* bl = (const uint4*)(g_owl + (size_t)kt * 32 * 64);
#pragma unroll
    for (int i = 0; i < 2; i++) {
        const int idx = tid + i * 128;   // 0..255
        sts128_sw(tbase + 32768u, idx, bh[idx]);
        sts128_sw(tbase + 36864u, idx, bl[idx]);
    }
}

__device__ __forceinline__ void issue_off_chunk(uint32_t tmem, uint32_t tbase, uint32_t mbar, bool first) {
#if HAS_TC
    asm volatile("fence.proxy.async;" ::: "memory");
    const uint64_t ah = sdesc(tbase);
    const uint64_t al = sdesc(tbase + 16384u);
    const uint64_t bh = sdesc(tbase + 32768u);
    const uint64_t bl = sdesc(tbase + 36864u);
#pragma unroll
    for (int s = 0; s < 4; s++) mma_bf16_ss(tmem, ah + 2 * s, bh + 2 * s, IDESC32_, (s == 0 && first) ? 0u : 1u);
#pragma unroll
    for (int s = 0; s < 4; s++) mma_bf16_ss(tmem, ah + 2 * s, bl + 2 * s, IDESC32_, 1u);
#pragma unroll
    for (int s = 0; s < 4; s++) mma_bf16_ss(tmem, al + 2 * s, bh + 2 * s, IDESC32_, 1u);
    TCGEN05_COMMIT(mbar);
#endif
}

__global__ __launch_bounds__(128, 1) void k_offconv_tc(const float* __restrict__ ob) {
#if HAS_TC
    extern __shared__ char smem[];
    const uint32_t sb = smem_u32(smem);
    const int tid = (int)threadIdx.x;
    const int wid = tid >> 5, lid = tid & 31;
    const int p0  = blockIdx.x * 128;
    const int b   = blockIdx.y;
    const uint32_t mb0 = sb + 16, mb1 = sb + 24;
    const uint32_t T0 = sb + 1024;

    if (tid == 0) { MBARRIER_INIT(mb0, 1); MBARRIER_INIT(mb1, 1); }
    if (wid == 0) TCGEN05_ALLOC(sb, 64);
    __syncthreads();
    uint32_t tmem;
    asm volatile("ld.shared.b32 %0, [%1];" : "=r"(tmem) : "r"(sb));

    build_off_stage(T0, 0, b, p0, tid);
    __syncthreads();

    int ph0 = 0, ph1 = 0;
    for (int kt = 0; kt < KT_; kt++) {
        const int cur = kt & 1;
        if (wid == 0 && elect1())
            issue_off_chunk(tmem, T0 + (uint32_t)cur * OFF_STG, cur ? mb1 : mb0, kt == 0);
        if (kt + 1 < KT_) {
            const int nxt = cur ^ 1;
            if (kt >= 1) {
                if (nxt == 0) { MBARRIER_WAIT_PARITY(mb0, ph0); ph0 ^= 1; }
                else          { MBARRIER_WAIT_PARITY(mb1, ph1); ph1 ^= 1; }
            }
            build_off_stage(T0 + (uint32_t)nxt * OFF_STG, kt + 1, b, p0, tid);
            __syncthreads();
        }
    }
    MBARRIER_WAIT_PARITY(mb0, ph0);
    MBARRIER_WAIT_PARITY(mb1, ph1);
    TCGEN05_FENCE_AFTER();

    // epilogue: lane = pixel (wid*32+lid), cols 0..31 = 27 offset channels
    uint32_t r[32];
    TCGEN05_LD_X32(r, tmem);
    TCGEN05_WAIT_LD();
    TCGEN05_FENCE_BEFORE();

    const int p  = p0 + wid * 32 + lid;
    const int py = p >> 6, px = p & 63;
#pragma unroll
    for (int k = 0; k < 9; k++) {
        const int kx = k % 3, ky = k / 3;
        const float ox = __uint_as_float(r[k])      + ob[k];
        const float oy = __uint_as_float(r[9 + k])  + ob[9 + k];
        const float om = __uint_as_float(r[18 + k]) + ob[18 + k];
        const int gi = (b * 9 + k) * P_ + p;
        g_sx[gi]   = (float)(px - 1 + (kx - 1)) + ox;
        g_sy[gi]   = (float)(py - 1 + (ky - 1)) + oy;
        g_mask[gi] = 1.f / (1.f + expf(-om));
    }

    __syncthreads();
    if (tid == 0) { MBAR_INVAL(mb0); MBAR_INVAL(mb1); }
    if (wid == 0) { TCGEN05_RELINQ(); TCGEN05_DEALLOC(tmem, 64); }
#endif
}

// ---------------- kernel 4: coalesced bilinear im2col (NHWC gather) ----------
__global__ __launch_bounds__(256) void k_im2col_tc() {
    __shared__ uint32_t sOff[4][128];
    __shared__ float    sWgt[4][128];
    const int tid = threadIdx.x;
    const int p0  = blockIdx.x * 128;
    const int kt  = blockIdx.y;
    const int b   = blockIdx.z;
    const int k   = kt >> 2;
    const int c0  = (kt & 3) << 6;

    if (tid < 128) {
        const int gi = (b * 9 + k) * P_ + p0 + tid;
        const float sx = g_sx[gi], sy = g_sy[gi], m = g_mask[gi];
        const float x0f = floorf(sx), y0f = floorf(sy);
        const int x0 = (int)x0f, y0 = (int)y0f;
        const float wx1 = sx - x0f, wy1 = sy - y0f;
        const float wx0 = 1.f - wx1, wy0 = 1.f - wy1;
        const bool vx0 = (x0 >= 0) && (x0 < W_), vx1 = (x0 + 1 >= 0) && (x0 + 1 < W_);
        const bool vy0 = (y0 >= 0) && (y0 < H_), vy1 = (y0 + 1 >= 0) && (y0 + 1 < H_);
        const int cx0 = min(max(x0, 0), W_ - 1), cx1 = min(max(x0 + 1, 0), W_ - 1);
        const int cy0 = min(max(y0, 0), H_ - 1), cy1 = min(max(y0 + 1, 0), H_ - 1);
        sOff[0][tid] = (uint32_t)((((cy0 + 1) * PROW + cx0 + 1) * 256 + c0) * 4);
        sOff[1][tid] = (uint32_t)((((cy0 + 1) * PROW + cx1 + 1) * 256 + c0) * 4);
        sOff[2][tid] = (uint32_t)((((cy1 + 1) * PROW + cx0 + 1) * 256 + c0) * 4);
        sOff[3][tid] = (uint32_t)((((cy1 + 1) * PROW + cx1 + 1) * 256 + c0) * 4);
        sWgt[0][tid] = wx0 * wy0 * ((vx0 && vy0) ? m : 0.f);
        sWgt[1][tid] = wx1 * wy0 * ((vx1 && vy0) ? m : 0.f);
        sWgt[2][tid] = wx0 * wy1 * ((vx0 && vy1) ? m : 0.f);
        sWgt[3][tid] = wx1 * wy1 * ((vx1 && vy1) ? m : 0.f);
    }
    __syncthreads();

    const char* xb = (const char*)(g_xtp + (size_t)b * PN * 256);
    const int cp = tid & 31;
    uint32_t* oh = (uint32_t*)g_colh + (((size_t)b * KT_ + kt) * P_ + p0) * 32 + cp;
    uint32_t* ol = (uint32_t*)g_coll + (((size_t)b * KT_ + kt) * P_ + p0) * 32 + cp;

#pragma unroll
    for (int it = 0; it < 16; it++) {
        const int pl = it * 8 + (tid >> 5);
        const uint32_t cb = (uint32_t)cp * 8u;
        const float2 a0 = *(const float2*)(xb + sOff[0][pl] + cb);
        const float2 a1 = *(const float2*)(xb + sOff[1][pl] + cb);
        const float2 a2 = *(const float2*)(xb + sOff[2][pl] + cb);
        const float2 a3 = *(const float2*)(xb + sOff[3][pl] + cb);
        const float w0 = sWgt[0][pl], w1 = sWgt[1][pl], w2 = sWgt[2][pl], w3 = sWgt[3][pl];
        const float v0 = w0 * a0.x + w1 * a1.x + w2 * a2.x + w3 * a3.x;
        const float v1 = w0 * a0.y + w1 * a1.y + w2 * a2.y + w3 * a3.y;
        const __nv_bfloat16 h0 = __float2bfloat16(v0);
        const __nv_bfloat16 h1 = __float2bfloat16(v1);
        __nv_bfloat162 hh; hh.x = h0; hh.y = h1;
        __nv_bfloat162 ll;
        ll.x = __float2bfloat16(v0 - __bfloat162float(h0));
        ll.y = __float2bfloat16(v1 - __bfloat162float(h1));
        oh[(size_t)pl * 32] = *(const uint32_t*)&hh;
        ol[(size_t)pl * 32] = *(const uint32_t*)&ll;
    }
}

// ---------------- kernel 5: tcgen05 main GEMM, cp.async pipeline -------------
// Stage: Ah 16K | Al 16K | Bh 32K | Bl 32K = 98304 B; two stages.
__device__ __forceinline__ void load_stage_async(uint32_t tbase, int kt, int b, int oc0, int p0, int tid) {
    const size_t aoff = ((size_t)kt * OC_ + oc0) * 64;
    const uint4* ah = (const uint4*)(g_wh + aoff);
    const uint4* al = (const uint4*)(g_wl + aoff);
    const size_t boff = (((size_t)b * KT_ + kt) * P_ + p0) * 64;
    const uint4* bh = (const uint4*)(g_colh + boff);
    const uint4* bl = (const uint4*)(g_coll + boff);
#pragma unroll
    for (int i = 0; i < 4; i++) {
        const int idx = tid + i * 256;
        cpasync16_sw(tbase,          idx, ah + idx);
        cpasync16_sw(tbase + 16384u, idx, al + idx);
    }
#pragma unroll
    for (int i = 0; i < 8; i++) {
        const int idx = tid + i * 256;
        cpasync16_sw(tbase + 32768u, idx, bh + idx);
        cpasync16_sw(tbase + 65536u, idx, bl + idx);
    }
}

__device__ __forceinline__ void issue_chunk(uint32_t tmem, uint32_t tbase, uint32_t mbar, bool first) {
#if HAS_TC
    asm volatile("fence.proxy.async;" ::: "memory");
    const uint64_t ah = sdesc(tbase);
    const uint64_t al = sdesc(tbase + 16384u);
    const uint64_t bh = sdesc(tbase + 32768u);
    const uint64_t bl = sdesc(tbase + 65536u);
#pragma unroll
    for (int s = 0; s < 4; s++) mma_bf16_ss(tmem, ah + 2 * s, bh + 2 * s, IDESC256_, (s == 0 && first) ? 0u : 1u);
#pragma unroll
    for (int s = 0; s < 4; s++) mma_bf16_ss(tmem, ah + 2 * s, bl + 2 * s, IDESC256_, 1u);
#pragma unroll
    for (int s = 0; s < 4; s++) mma_bf16_ss(tmem, al + 2 * s, bh + 2 * s, IDESC256_, 1u);
    TCGEN05_COMMIT(mbar);
#endif
}

__global__ __launch_bounds__(256, 1) void k_gemm_tc(const float* __restrict__ bias,
                                                    float* __restrict__ out) {
#if HAS_TC
    extern __shared__ char smem[];
    const uint32_t sb = smem_u32(smem);
    const int tid = (int)threadIdx.x;
    const int wid = tid >> 5, lid = tid & 31;
    const int p0  = blockIdx.x * 256;
    const int oc0 = blockIdx.y * 128;
    const int b   = blockIdx.z;
    const uint32_t mb0 = sb + 16, mb1 = sb + 24;
    const uint32_t T0 = sb + 1024;

    if (tid == 0) { MBARRIER_INIT(mb0, 1); MBARRIER_INIT(mb1, 1); }
    if (wid == 0) TCGEN05_ALLOC(sb, 256);
    __syncthreads();
    uint32_t tmem;
    asm volatile("ld.shared.b32 %0, [%1];" : "=r"(tmem) : "r"(sb));

    load_stage_async(T0, 0, b, oc0, p0, tid);
    CP_COMMIT();

    int ph0 = 0, ph1 = 0;
    for (int kt = 0; kt < KT_; kt++) {
        const int cur = kt & 1;
        CP_WAIT0();
        __syncthreads();
        if (wid == 0 && elect1())
            issue_chunk(tmem, T0 + (uint32_t)cur * 98304u, cur ? mb1 : mb0, kt == 0);
        if (kt + 1 < KT_) {
            const int nxt = cur ^ 1;
            if (kt >= 1) {
                if (nxt == 0) { MBARRIER_WAIT_PARITY(mb0, ph0); ph0 ^= 1; }
                else          { MBARRIER_WAIT_PARITY(mb1, ph1); ph1 ^= 1; }
            }
            load_stage_async(T0 + (uint32_t)nxt * 98304u, kt + 1, b, oc0, p0, tid);
            CP_COMMIT();
        }
    }
    MBARRIER_WAIT_PARITY(mb0, ph0);
    MBARRIER_WAIT_PARITY(mb1, ph1);
    TCGEN05_FENCE_AFTER();

    // epilogue: 8 warps; subpartition = wid&3 (oc rows), column half = wid>>2
    const int sub = wid & 3, half = wid >> 2;
    const int oc = oc0 + sub * 32 + lid;
    const float bv = bias[oc];
    float* op = out + ((size_t)b * OC_ + oc) * P_ + p0 + half * 128;
#pragma unroll
    for (int j = 0; j < 4; j++) {
        uint32_t r[32];
        TCGEN05_LD_X32(r, tmem + half * 128 + j * 32);
        TCGEN05_WAIT_LD();
#pragma unroll
        for (int c = 0; c < 32; c += 4) {
            float4 v;
            v.x = __uint_as_float(r[c + 0]) + bv;
            v.y = __uint_as_float(r[c + 1]) + bv;
            v.z = __uint_as_float(r[c + 2]) + bv;
            v.w = __uint_as_float(r[c + 3]) + bv;
            *(float4*)(op + j * 32 + c) = v;
        }
    }
    TCGEN05_FENCE_BEFORE();
    __syncthreads();
    if (tid == 0) { MBAR_INVAL(mb0); MBAR_INVAL(mb1); }
    if (wid == 0) { TCGEN05_RELINQ(); TCGEN05_DEALLOC(tmem, 256); }
#endif
}

// ---------------- launch ----------------
extern "C" void kernel_launch(void* const* d_in, const int* in_sizes, int n_in,
                              void* d_out, int out_size) {
    const float* x    = (const float*)d_in[0];
    const float* ow   = (const float*)d_in[1];
    const float* ob   = (const float*)d_in[2];
    const float* wgt  = (const float*)d_in[3];
    const float* bias = (const float*)d_in[4];
    float* out = (float*)d_out;

    cudaFuncSetAttribute(k_gemm_tc,    cudaFuncAttributeMaxDynamicSharedMemorySize, 197632);
    cudaFuncSetAttribute(k_offconv_tc, cudaFuncAttributeMaxDynamicSharedMemorySize, 83968);

    k_zero_border<<<dim3(260, B_), 64>>>();
    k_transpose<<<dim3(64, 2, B_), 256>>>(x);
    k_wsplit<<<(OC_ * CK_) / 256, 256>>>(wgt);
    k_woffsplit<<<(KT_ * 32 * 64) / 256, 256>>>(ow);
    k_offconv_tc<<<dim3(32, B_), 128, 83968>>>(ob);
    k_im2col_tc<<<dim3(P_ / 128, KT_, B_), 256>>>();
    k_gemm_tc<<<dim3(P_ / 256, OC_ / 128, B_), 256, 197632>>>(bias, out);
}